// round 5
// baseline (speedup 1.0000x reference)
#include <cuda_runtime.h>
#include <cuda_bf16.h>
#include <cstdint>

// ---------------------------------------------------------------------------
// MoE layer (T=16384, D=1024, E=8, top-2). bf16x3 mma.sync grouped GEMMs.
// R5: GEMM = 128-thread CTAs (BM=64), 2-stage cp.async, 1 sync/iter, occ 3.
// ---------------------------------------------------------------------------

namespace {
constexpr int TT = 16384;
constexpr int DD = 1024;
constexpr int NE = 8;
constexpr int NP = TT * 2;          // 32768
constexpr int MAXT = 520;           // 32768/64 + 8 slack

constexpr int BM = 64, BN = 128, BK = 32;
constexpr int KT = DD / BK;         // 32
constexpr int NSTAGE = 2;

constexpr int SAK = 40;             // A smem row stride (bf16 elems)
constexpr int SBN = 136;            // B smem row stride (bf16 elems)
constexpr int OFF_AH = 0;                       // 64*40*2  = 5120
constexpr int OFF_AL = 5120;
constexpr int OFF_BH = 10240;                   // 32*136*2 = 8704
constexpr int OFF_BL = 18944;
constexpr int STAGE  = 27648;
constexpr int SMEM_BYTES = NSTAGE * STAGE;      // 55296 -> 3 CTAs/SM
} // namespace

// ------------------------- device scratch (static) -------------------------
__device__ int g_counts[NE];
__device__ int g_offsets[NE + 1];
__device__ int g_cursor[NE];
__device__ int g_pair_expert[NP];
__device__ float g_pair_w[NP];
__device__ int g_bucket_pair[NP];
__device__ int g_row_of_pair[NP];
__device__ int g_tile_e[MAXT];
__device__ int g_tile_row[MAXT];
__device__ int g_num_tiles;

__device__ __nv_bfloat16 g_Whi[3ull * NE * DD * DD];  // [sec][e][k][n]
__device__ __nv_bfloat16 g_Wlo[3ull * NE * DD * DD];
__device__ __nv_bfloat16 g_Xhi[(size_t)NP * DD];
__device__ __nv_bfloat16 g_Xlo[(size_t)NP * DD];
__device__ float g_t1[(size_t)NP * DD];
__device__ float g_t2[(size_t)NP * DD];
__device__ __nv_bfloat16 g_A2hi[(size_t)NP * DD];
__device__ __nv_bfloat16 g_A2lo[(size_t)NP * DD];

// ------------------------------- helpers -----------------------------------
__device__ __forceinline__ uint32_t smem_u32(const void* p) {
    return (uint32_t)__cvta_generic_to_shared(p);
}
__device__ __forceinline__ void cp16(uint32_t s, const void* g, bool pred) {
    int sz = pred ? 16 : 0;
    asm volatile("cp.async.cg.shared.global [%0], [%1], 16, %2;\n"
                 :: "r"(s), "l"(g), "r"(sz));
}
__device__ __forceinline__ void ldsm4(uint32_t* r, uint32_t addr) {
    asm volatile("ldmatrix.sync.aligned.m8n8.x4.shared.b16 {%0,%1,%2,%3}, [%4];"
                 : "=r"(r[0]), "=r"(r[1]), "=r"(r[2]), "=r"(r[3]) : "r"(addr));
}
__device__ __forceinline__ void ldsm2t(uint32_t* r, uint32_t addr) {
    asm volatile("ldmatrix.sync.aligned.m8n8.x2.trans.shared.b16 {%0,%1}, [%2];"
                 : "=r"(r[0]), "=r"(r[1]) : "r"(addr));
}
__device__ __forceinline__ void mma_bf16(float* c, const uint32_t* a, const uint32_t* b) {
    asm volatile(
        "mma.sync.aligned.m16n8k16.row.col.f32.bf16.bf16.f32 "
        "{%0,%1,%2,%3}, {%4,%5,%6,%7}, {%8,%9}, {%0,%1,%2,%3};\n"
        : "+f"(c[0]), "+f"(c[1]), "+f"(c[2]), "+f"(c[3])
        : "r"(a[0]), "r"(a[1]), "r"(a[2]), "r"(a[3]), "r"(b[0]), "r"(b[1]));
}
__device__ __forceinline__ void split2(float v, __nv_bfloat16& h, __nv_bfloat16& l) {
    h = __float2bfloat16_rn(v);
    l = __float2bfloat16_rn(v - __bfloat162float(h));
}

// ------------------------------- small kernels ------------------------------
__global__ void init_kernel() {
    int i = threadIdx.x;
    if (i < NE) g_counts[i] = 0;
}

__global__ void router_kernel(const float* __restrict__ x,
                              const float* __restrict__ rw,
                              const float* __restrict__ rb) {
    int warp = threadIdx.x >> 5;
    int lane = threadIdx.x & 31;
    int token = blockIdx.x * (blockDim.x >> 5) + warp;
    if (token >= TT) return;

    const float4* xr = (const float4*)(x + (size_t)token * DD);
    float acc[NE];
    #pragma unroll
    for (int e = 0; e < NE; e++) acc[e] = 0.f;
    for (int i = lane; i < DD / 4; i += 32) {
        float4 v = xr[i];
        const float* r0 = rw + i * 4 * NE;
        #pragma unroll
        for (int e = 0; e < NE; e++)
            acc[e] += v.x * r0[e] + v.y * r0[NE + e] + v.z * r0[2 * NE + e] + v.w * r0[3 * NE + e];
    }
    #pragma unroll
    for (int off = 16; off; off >>= 1)
        #pragma unroll
        for (int e = 0; e < NE; e++)
            acc[e] += __shfl_xor_sync(0xFFFFFFFFu, acc[e], off);

    if (lane == 0) {
        #pragma unroll
        for (int e = 0; e < NE; e++) acc[e] += rb[e];
        int i0 = 0;
        #pragma unroll
        for (int e = 1; e < NE; e++) if (acc[e] > acc[i0]) i0 = e;
        int i1 = (i0 == 0) ? 1 : 0;
        #pragma unroll
        for (int e = 0; e < NE; e++) if (e != i0 && acc[e] > acc[i1]) i1 = e;
        float w0 = 1.f / (1.f + __expf(acc[i1] - acc[i0]));
        g_pair_expert[2 * token] = i0;     g_pair_w[2 * token] = w0;
        g_pair_expert[2 * token + 1] = i1; g_pair_w[2 * token + 1] = 1.f - w0;
        atomicAdd(&g_counts[i0], 1);
        atomicAdd(&g_counts[i1], 1);
    }
}

__global__ void scan_kernel() {
    if (threadIdx.x != 0 || blockIdx.x != 0) return;
    int off = 0;
    for (int e = 0; e < NE; e++) { g_offsets[e] = off; g_cursor[e] = off; off += g_counts[e]; }
    g_offsets[NE] = off;
    int nt = 0;
    for (int e = 0; e < NE; e++) {
        int base = g_offsets[e], m = g_counts[e];
        for (int mb = 0; mb < m; mb += BM) { g_tile_e[nt] = e; g_tile_row[nt] = base + mb; nt++; }
    }
    g_num_tiles = nt;
}

__global__ void scatter_kernel() {
    int p = blockIdx.x * blockDim.x + threadIdx.x;
    if (p >= NP) return;
    int e = g_pair_expert[p];
    int s = atomicAdd(&g_cursor[e], 1);
    g_bucket_pair[s] = p;
    g_row_of_pair[p] = s;
}

__global__ void wsplit_kernel(const float* __restrict__ src,
                              __nv_bfloat16* __restrict__ dhi,
                              __nv_bfloat16* __restrict__ dlo) {
    size_t idx = (size_t)blockIdx.x * blockDim.x + threadIdx.x;
    size_t base = idx * 4;
    float4 v = *(const float4*)(src + base);
    __nv_bfloat16 h0, h1, h2, h3, l0, l1, l2, l3;
    split2(v.x, h0, l0); split2(v.y, h1, l1); split2(v.z, h2, l2); split2(v.w, h3, l3);
    __nv_bfloat162* ph = (__nv_bfloat162*)(dhi + base);
    __nv_bfloat162* pl = (__nv_bfloat162*)(dlo + base);
    ph[0] = __nv_bfloat162(h0, h1); ph[1] = __nv_bfloat162(h2, h3);
    pl[0] = __nv_bfloat162(l0, l1); pl[1] = __nv_bfloat162(l2, l3);
}

__global__ void xgather_kernel(const float* __restrict__ x) {
    size_t idx = (size_t)blockIdx.x * blockDim.x + threadIdx.x;
    int s = (int)(idx >> 8);
    int d = (int)(idx & 255) * 4;
    int t = g_bucket_pair[s] >> 1;
    float4 v = *(const float4*)(x + (size_t)t * DD + d);
    __nv_bfloat16 h0, h1, h2, h3, l0, l1, l2, l3;
    split2(v.x, h0, l0); split2(v.y, h1, l1); split2(v.z, h2, l2); split2(v.w, h3, l3);
    size_t base = (size_t)s * DD + d;
    *(__nv_bfloat162*)(g_Xhi + base)     = __nv_bfloat162(h0, h1);
    *(__nv_bfloat162*)(g_Xhi + base + 2) = __nv_bfloat162(h2, h3);
    *(__nv_bfloat162*)(g_Xlo + base)     = __nv_bfloat162(l0, l1);
    *(__nv_bfloat162*)(g_Xlo + base + 2) = __nv_bfloat162(l2, l3);
}

__global__ void act_kernel() {
    size_t idx = (size_t)blockIdx.x * blockDim.x + threadIdx.x;
    size_t base = idx * 4;
    float4 g = *(const float4*)(g_t1 + base);
    float4 u = *(const float4*)(g_t2 + base);
    float4 a;
    a.x = u.x * g.x / (1.f + __expf(-g.x));
    a.y = u.y * g.y / (1.f + __expf(-g.y));
    a.z = u.z * g.z / (1.f + __expf(-g.z));
    a.w = u.w * g.w / (1.f + __expf(-g.w));
    __nv_bfloat16 h0, h1, h2, h3, l0, l1, l2, l3;
    split2(a.x, h0, l0); split2(a.y, h1, l1); split2(a.z, h2, l2); split2(a.w, h3, l3);
    *(__nv_bfloat162*)(g_A2hi + base)     = __nv_bfloat162(h0, h1);
    *(__nv_bfloat162*)(g_A2hi + base + 2) = __nv_bfloat162(h2, h3);
    *(__nv_bfloat162*)(g_A2lo + base)     = __nv_bfloat162(l0, l1);
    *(__nv_bfloat162*)(g_A2lo + base + 2) = __nv_bfloat162(l2, l3);
}

__global__ void combine_kernel(float* __restrict__ out) {
    size_t idx = (size_t)blockIdx.x * blockDim.x + threadIdx.x;
    int t = (int)(idx >> 8);
    int d = (int)(idx & 255) * 4;
    int r0 = g_row_of_pair[2 * t];
    int r1 = g_row_of_pair[2 * t + 1];
    float w0 = g_pair_w[2 * t];
    float w1 = g_pair_w[2 * t + 1];
    float4 y0 = *(const float4*)(g_t1 + (size_t)r0 * DD + d);
    float4 y1 = *(const float4*)(g_t1 + (size_t)r1 * DD + d);
    float4 o;
    o.x = w0 * y0.x + w1 * y1.x;
    o.y = w0 * y0.y + w1 * y1.y;
    o.z = w0 * y0.z + w1 * y1.z;
    o.w = w0 * y0.w + w1 * y1.w;
    *(float4*)(out + (size_t)t * DD + d) = o;
}

// ------------------- grouped GEMM (bf16x3, 128 thr, occ 3) ------------------
__global__ void __launch_bounds__(128, 3)
gemm_kernel(const __nv_bfloat16* __restrict__ Ahi,
            const __nv_bfloat16* __restrict__ Alo,
            const __nv_bfloat16* __restrict__ Wsec_hi,
            const __nv_bfloat16* __restrict__ Wsec_lo,
            float* __restrict__ Cout) {
    int tile = blockIdx.y;
    if (tile >= g_num_tiles) return;
    int e = g_tile_e[tile];
    int row0 = g_tile_row[tile];
    int row_end = g_offsets[e + 1];
    int n0 = blockIdx.x * BN;
    const __nv_bfloat16* Bhi = Wsec_hi + (size_t)e * DD * DD;
    const __nv_bfloat16* Blo = Wsec_lo + (size_t)e * DD * DD;

    extern __shared__ char smem[];
    uint32_t sb = smem_u32(smem);

    int tid = threadIdx.x;
    int wn = tid >> 5, lane = tid & 31;      // 4 warps: warp n-slice = wn*32
    int r16 = lane & 15, c8 = lane >> 4;

    float C[4][4][4];
    #pragma unroll
    for (int mf = 0; mf < 4; mf++)
        #pragma unroll
        for (int nf = 0; nf < 4; nf++)
            #pragma unroll
            for (int i = 0; i < 4; i++) C[mf][nf][i] = 0.f;

    auto issue = [&](int kt, int buf) {
        int kb = kt * BK;
        uint32_t st = sb + buf * STAGE;
        #pragma unroll
        for (int i = 0; i < 2; i++) {           // A hi+lo: 256 vec each
            int v = tid + i * 128;
            int r = v >> 2, kv = (v & 3) * 8;
            int gr = row0 + r;
            bool ok = gr < row_end;
            int grc = ok ? gr : row0;
            size_t go = (size_t)grc * DD + kb + kv;
            uint32_t so = (uint32_t)((r * SAK + kv) * 2);
            cp16(st + OFF_AH + so, Ahi + go, ok);
            cp16(st + OFF_AL + so, Alo + go, ok);
        }
        #pragma unroll
        for (int i = 0; i < 4; i++) {           // B hi+lo: 512 vec each
            int v = tid + i * 128;
            int kr = v >> 4, nv = (v & 15) * 8;
            size_t go = (size_t)(kb + kr) * DD + n0 + nv;
            uint32_t so = (uint32_t)((kr * SBN + nv) * 2);
            cp16(st + OFF_BH + so, Bhi + go, true);
            cp16(st + OFF_BL + so, Blo + go, true);
        }
        asm volatile("cp.async.commit_group;\n");
    };

    auto compute = [&](int buf) {
        uint32_t st = sb + buf * STAGE;
        #pragma unroll
        for (int kk = 0; kk < 2; kk++) {
            uint32_t ah[4][4], al[4][4], bh[4][2], bl[4][2];
            #pragma unroll
            for (int mf = 0; mf < 4; mf++) {
                uint32_t off = (uint32_t)(((mf * 16 + r16) * SAK + kk * 16 + c8 * 8) * 2);
                ldsm4(ah[mf], st + OFF_AH + off);
                ldsm4(al[mf], st + OFF_AL + off);
            }
            #pragma unroll
            for (int nf = 0; nf < 4; nf++) {
                uint32_t off = (uint32_t)(((kk * 16 + r16) * SBN + wn * 32 + nf * 8) * 2);
                ldsm2t(bh[nf], st + OFF_BH + off);
                ldsm2t(bl[nf], st + OFF_BL + off);
            }
            #pragma unroll
            for (int mf = 0; mf < 4; mf++)
                #pragma unroll
                for (int nf = 0; nf < 4; nf++) {
                    mma_bf16(C[mf][nf], ah[mf], bh[nf]);
                    mma_bf16(C[mf][nf], ah[mf], bl[nf]);
                    mma_bf16(C[mf][nf], al[mf], bh[nf]);
                }
        }
    };

    // 2-stage: load k+1 overlaps compute k; one sync per iter.
    issue(0, 0);
    #pragma unroll 1
    for (int kt = 0; kt < KT; kt++) {
        asm volatile("cp.async.wait_group 0;\n");
        __syncthreads();
        if (kt + 1 < KT) issue(kt + 1, (kt + 1) & 1);
        compute(kt & 1);
    }

    #pragma unroll
    for (int mf = 0; mf < 4; mf++) {
        int r = row0 + mf * 16 + (lane >> 2);
        #pragma unroll
        for (int nf = 0; nf < 4; nf++) {
            int c = n0 + wn * 32 + nf * 8 + (lane & 3) * 2;
            float* p = Cout + (size_t)r * DD + c;
            if (r < row_end)     { p[0] = C[mf][nf][0]; p[1] = C[mf][nf][1]; }
            if (r + 8 < row_end) { p[8 * DD] = C[mf][nf][2]; p[8 * DD + 1] = C[mf][nf][3]; }
        }
    }
}

// ------------------------------ launcher ------------------------------------
extern "C" void kernel_launch(void* const* d_in, const int* in_sizes, int n_in,
                              void* d_out, int out_size) {
    const float* x  = (const float*)d_in[0];
    const float* rw = (const float*)d_in[1];
    const float* rb = (const float*)d_in[2];
    const float* wg = (const float*)d_in[3];
    const float* wu = (const float*)d_in[4];
    const float* wd = (const float*)d_in[5];
    float* out = (float*)d_out;

    cudaFuncSetAttribute(gemm_kernel, cudaFuncAttributeMaxDynamicSharedMemorySize, SMEM_BYTES);

    __nv_bfloat16 *whi_p, *wlo_p, *xhi_p, *xlo_p, *a2hi_p, *a2lo_p;
    float *t1_p, *t2_p;
    cudaGetSymbolAddress((void**)&whi_p, g_Whi);
    cudaGetSymbolAddress((void**)&wlo_p, g_Wlo);
    cudaGetSymbolAddress((void**)&xhi_p, g_Xhi);
    cudaGetSymbolAddress((void**)&xlo_p, g_Xlo);
    cudaGetSymbolAddress((void**)&a2hi_p, g_A2hi);
    cudaGetSymbolAddress((void**)&a2lo_p, g_A2lo);
    cudaGetSymbolAddress((void**)&t1_p, g_t1);
    cudaGetSymbolAddress((void**)&t2_p, g_t2);

    const size_t WSEC = (size_t)NE * DD * DD;

    init_kernel<<<1, 32>>>();
    router_kernel<<<TT / 8, 256>>>(x, rw, rb);
    scan_kernel<<<1, 1>>>();
    scatter_kernel<<<NP / 256, 256>>>();

    wsplit_kernel<<<(unsigned)(WSEC / 4 / 256), 256>>>(wg, whi_p + 0 * WSEC, wlo_p + 0 * WSEC);
    wsplit_kernel<<<(unsigned)(WSEC / 4 / 256), 256>>>(wu, whi_p + 1 * WSEC, wlo_p + 1 * WSEC);
    wsplit_kernel<<<(unsigned)(WSEC / 4 / 256), 256>>>(wd, whi_p + 2 * WSEC, wlo_p + 2 * WSEC);

    xgather_kernel<<<(unsigned)((size_t)NP * DD / 4 / 256), 256>>>(x);

    dim3 ggrid(DD / BN, MAXT);
    gemm_kernel<<<ggrid, 128, SMEM_BYTES>>>(xhi_p, xlo_p, whi_p + 0 * WSEC, wlo_p + 0 * WSEC, t1_p);
    gemm_kernel<<<ggrid, 128, SMEM_BYTES>>>(xhi_p, xlo_p, whi_p + 1 * WSEC, wlo_p + 1 * WSEC, t2_p);

    act_kernel<<<(unsigned)((size_t)NP * DD / 4 / 256), 256>>>();

    gemm_kernel<<<ggrid, 128, SMEM_BYTES>>>(a2hi_p, a2lo_p, whi_p + 2 * WSEC, wlo_p + 2 * WSEC, t1_p);

    combine_kernel<<<(unsigned)((size_t)TT * DD / 4 / 256), 256>>>(out);
}